// round 13
// baseline (speedup 1.0000x reference)
#include <cuda_runtime.h>
#include <cuda_fp16.h>
#include <math.h>
#include <stdint.h>

// ---------------------------------------------------------------------------
// AuxLossFreeGate, fused GEMM+gate, warp-autonomous mainloop (NO block syncs):
//   CTA = 32 tokens x 256 experts, 256 threads, 2 CTAs/SM.
//   Each warp owns 32 tokens x 32 experts (2 m-tiles x 4 n-tiles, 3 planes).
//   B: per-warp cp.async slice from pre-split W image into a private SMEM
//      region; per-thread wait_group + __syncwarp only.
//   A: mma fragments LDG'd directly from X (L1-cached, 8x warp reuse) and
//      fp16 2-way split (v = v1 + v2*2^-12) in registers.
//   Gate runs in-CTA from SMEM scores overlay (two block syncs total).
// ---------------------------------------------------------------------------

#define N_EXPERTS   256
#define DIM_K       2048
#define N_GROUPS    8
#define TOPK        8
#define TOPK_GROUPS 4
#define ROUTE_SCALE 2.5f
#define MAX_T       32768
#define NEG_INF_F   (-1e30f)

// ---------------- GEMM config ----------------
#define KC       32
#define NCHUNK   (DIM_K / KC)
#define BBLK     64                       // u32 per (nt,ks) block (16B clean)
#define BPLANE   4096                     // u32 per plane per chunk (32nt*2ks*64)
#define BCHUNK   8192                     // u32 per chunk in image (2 planes)
#define WSLICE   512                      // u32 per warp per plane per chunk
#define WBUF     1024                     // u32 per warp per buffer (2 planes)
#define SMEM_U32 (2 * 8 * WBUF)           // 16384 u32 = 64 KB (2 bufs x 8 warps)
#define SC_STRIDE 264
#define SMEM_BYTES (SMEM_U32 * 4)

#define NTHREADS 256

// W image: [chunk(64)][plane(2)][nt*2+ks (64)][64], BBLK=64.
__device__ __align__(16) uint32_t g_wimg[NCHUNK * BCHUNK];

#define MMA_F16(d, a, b) asm volatile( \
    "mma.sync.aligned.m16n8k16.row.col.f32.f16.f16.f32 " \
    "{%0,%1,%2,%3},{%4,%5,%6,%7},{%8,%9},{%0,%1,%2,%3};" \
    : "+f"((d)[0]), "+f"((d)[1]), "+f"((d)[2]), "+f"((d)[3]) \
    : "r"((a).x), "r"((a).y), "r"((a).z), "r"((a).w), "r"((b).x), "r"((b).y))

#define CP_ASYNC16(dst_u32, src_ptr) \
    asm volatile("cp.async.cg.shared.global [%0], [%1], 16;" \
                 :: "r"(dst_u32), "l"(src_ptr) : "memory")
#define CP_COMMIT()  asm volatile("cp.async.commit_group;" ::: "memory")
#define CP_WAIT0()   asm volatile("cp.async.wait_group 0;" ::: "memory")
#define CP_WAIT1()   asm volatile("cp.async.wait_group 1;" ::: "memory")

__device__ __forceinline__ uint32_t smem_to_u32(const void* p) {
    uint32_t a;
    asm("{ .reg .u64 t; cvta.to.shared.u64 t, %1; cvt.u32.u64 %0, t; }" : "=r"(a) : "l"(p));
    return a;
}

// fp16 2-way split of a float pair -> plane1/plane2 packed half2 words.
// Identical numerics to the validated hsplit4 (per element).
__device__ __forceinline__ void hsplit2(float x, float y, uint32_t& p1, uint32_t& p2)
{
    __half2 h1 = __floats2half2_rn(x, y);
    p1 = *(uint32_t*)&h1;
    float rx = (x - __half2float(__low2half(h1)))  * 4096.0f;
    float ry = (y - __half2float(__high2half(h1))) * 4096.0f;
    __half2 h2 = __floats2half2_rn(rx, ry);
    p2 = *(uint32_t*)&h2;
}

__device__ __forceinline__ float sigf(float v) { return 1.0f / (1.0f + expf(-v)); }

__device__ __forceinline__ uint32_t fkey(float f) {
    uint32_t u = __float_as_uint(f);
    return u ^ (uint32_t)(((int32_t)u >> 31) | 0x80000000);
}

// ---------------------------------------------------------------------------
// Kernel 0: pre-split W into fragment-image layout (BBLK=64 variant).
// ---------------------------------------------------------------------------
__global__ __launch_bounds__(256)
void wsplit_kernel(const float* __restrict__ W)
{
    const int gid = blockIdx.x * 256 + threadIdx.x;   // 0..262143
    const int n = gid >> 10;                          // expert 0..255
    const int p = gid & 1023;                         // k-pair
    const int k = 2 * p;

    float2 w = *(const float2*)(W + (size_t)n * DIM_K + k);
    uint32_t p1, p2;
    hsplit2(w.x, w.y, p1, p2);

    const int nt = n >> 3;
    const int cn = n & 7;
    const int c  = k >> 5;
    const int kk = k & 31;
    const int ks = kk >> 4;
    const int kb = kk & 15;
    const int slot = cn * 4 + ((kb >> 1) & 3);
    const int reg  = kb >> 3;

    const int base = c * BCHUNK + (nt * 2 + ks) * BBLK + slot * 2 + reg;
    g_wimg[base]          = p1;
    g_wimg[base + BPLANE] = p2;
}

// ---------------------------------------------------------------------------
// Kernel 1: fused GEMM + gate, warp-autonomous. 256 threads, 8 warps.
// ---------------------------------------------------------------------------
__global__ __launch_bounds__(NTHREADS, 2)
void fused_kernel(const float* __restrict__ X, const float* __restrict__ bias,
                  float* __restrict__ out_w, float* __restrict__ out_i)
{
    extern __shared__ uint32_t sm[];
    const uint32_t smem_base = smem_to_u32(sm);
    const int tid  = threadIdx.x;
    const int warp = tid >> 5;
    const int lane = tid & 31;

    const int mt_blk = blockIdx.x;                  // 32-token tile
    const float* xb = X + (size_t)mt_blk * 32 * DIM_K;

    // A fragment geometry (per lane): rows r0/r0+8, k pair columns
    const int arow = lane >> 2;                     // 0..7
    const int acol = (lane & 3) * 2;                // 0,2,4,6

    float accM[2][4][4], accS[2][4][4];
#pragma unroll
    for (int mi = 0; mi < 2; ++mi)
#pragma unroll
        for (int ni = 0; ni < 4; ++ni)
#pragma unroll
            for (int q = 0; q < 4; ++q) { accM[mi][ni][q] = 0.f; accS[mi][ni][q] = 0.f; }

    // per-warp B region bases
    const uint32_t wreg0 = smem_base + (0 * 8 + warp) * WBUF * 4;   // buf 0
    const uint32_t wreg1 = smem_base + (1 * 8 + warp) * WBUF * 4;   // buf 1
    const uint32_t* wsrc = g_wimg + warp * WSLICE;                  // plane0 slice

    // ---- prologue: issue B(0) into buf 0 ----
#pragma unroll
    for (int q = 0; q < 2; ++q)
#pragma unroll
        for (int j = 0; j < 4; ++j)
            CP_ASYNC16(wreg0 + (q * WSLICE + j * 128 + lane * 4) * 4,
                       wsrc + q * BPLANE + j * 128 + lane * 4);
    CP_COMMIT();

    for (int c = 0; c < NCHUNK; ++c) {
        const int buf = c & 1;
        const uint32_t wr = buf ? wreg1 : wreg0;

        // ---- issue B(c+1) into the other private buffer; wait for B(c) ----
        if (c + 1 < NCHUNK) {
            const uint32_t wn = buf ? wreg0 : wreg1;
            const uint32_t* src = wsrc + (c + 1) * BCHUNK;
#pragma unroll
            for (int q = 0; q < 2; ++q)
#pragma unroll
                for (int j = 0; j < 4; ++j)
                    CP_ASYNC16(wn + (q * WSLICE + j * 128 + lane * 4) * 4,
                               src + q * BPLANE + j * 128 + lane * 4);
            CP_COMMIT();
            CP_WAIT1();                              // B(c) complete
        } else {
            CP_WAIT0();                              // last chunk
        }
        __syncwarp();

        // ---- compute chunk c ----
        const int kbase = c * KC;
#pragma unroll
        for (int ks = 0; ks < 2; ++ks) {
            // A fragments: direct LDG + register split (both m-tiles)
            uint4 af[2][2];                          // [plane][m-tile]
#pragma unroll
            for (int mi = 0; mi < 2; ++mi) {
                const int r0 = mi * 16 + arow;
                const int k0 = kbase + ks * 16 + acol;
                float2 a00 = *(const float2*)(xb + r0 * DIM_K + k0);
                float2 a10 = *(const float2*)(xb + (r0 + 8) * DIM_K + k0);
                float2 a01 = *(const float2*)(xb + r0 * DIM_K + k0 + 8);
                float2 a11 = *(const float2*)(xb + (r0 + 8) * DIM_K + k0 + 8);
                hsplit2(a00.x, a00.y, af[0][mi].x, af[1][mi].x);
                hsplit2(a10.x, a10.y, af[0][mi].y, af[1][mi].y);
                hsplit2(a01.x, a01.y, af[0][mi].z, af[1][mi].z);
                hsplit2(a11.x, a11.y, af[0][mi].w, af[1][mi].w);
            }

            // B fragments from private SMEM region
            uint2 bf[4][2];                          // [n-tile][plane]
            const uint32_t* wsm = (const uint32_t*)0;
#pragma unroll
            for (int ni = 0; ni < 4; ++ni) {
                const uint32_t off = ((ni * 2 + ks) * BBLK + lane * 2) * 4;
                asm volatile("ld.shared.v2.u32 {%0, %1}, [%2];"
                             : "=r"(bf[ni][0].x), "=r"(bf[ni][0].y)
                             : "r"(wr + off));
                asm volatile("ld.shared.v2.u32 {%0, %1}, [%2];"
                             : "=r"(bf[ni][1].x), "=r"(bf[ni][1].y)
                             : "r"(wr + WSLICE * 4 + off));
            }
            (void)wsm;

#pragma unroll
            for (int mi = 0; mi < 2; ++mi)
#pragma unroll
                for (int ni = 0; ni < 4; ++ni)
                    MMA_F16(accM[mi][ni], af[0][mi], bf[ni][0]);
#pragma unroll
            for (int mi = 0; mi < 2; ++mi)
#pragma unroll
                for (int ni = 0; ni < 4; ++ni)
                    MMA_F16(accS[mi][ni], af[0][mi], bf[ni][1]);
#pragma unroll
            for (int mi = 0; mi < 2; ++mi)
#pragma unroll
                for (int ni = 0; ni < 4; ++ni)
                    MMA_F16(accS[mi][ni], af[1][mi], bf[ni][0]);
        }
    }

    // ---- epilogue 1: sigmoid scores -> SMEM overlay (32 x 256) ----
    __syncthreads();                                 // B buffers dead
    float* scs = (float*)sm;
    const float INV = 1.0f / 4096.0f;
    const int rbase = lane >> 2;
    const int cbase = warp * 32 + (lane & 3) * 2;
#pragma unroll
    for (int mi = 0; mi < 2; ++mi) {
#pragma unroll
        for (int ni = 0; ni < 4; ++ni) {
            const int rr = rbase + mi * 16;
            const int cc = cbase + ni * 8;
            float2 v0, v1;
            v0.x = sigf(fmaf(accS[mi][ni][0], INV, accM[mi][ni][0]));
            v0.y = sigf(fmaf(accS[mi][ni][1], INV, accM[mi][ni][1]));
            v1.x = sigf(fmaf(accS[mi][ni][2], INV, accM[mi][ni][2]));
            v1.y = sigf(fmaf(accS[mi][ni][3], INV, accM[mi][ni][3]));
            *(float2*)&scs[rr * SC_STRIDE + cc] = v0;
            *(float2*)&scs[(rr + 8) * SC_STRIDE + cc] = v1;
        }
    }
    __syncthreads();

    // ---- epilogue 2: gate 4 tokens per warp (validated logic) ----
    float4 bb0 = *(const float4*)(bias + lane * 8);
    float4 bb1 = *(const float4*)(bias + lane * 8 + 4);

    for (int tt = 0; tt < 4; ++tt) {
        const int row = warp * 4 + tt;
        const float* srow = scs + row * SC_STRIDE;

        float s[8], b[8];
        {
            float4 s0 = *(const float4*)(srow + lane * 8);
            float4 s1 = *(const float4*)(srow + lane * 8 + 4);
            s[0]=s0.x; s[1]=s0.y; s[2]=s0.z; s[3]=s0.w;
            s[4]=s1.x; s[5]=s1.y; s[6]=s1.z; s[7]=s1.w;
            b[0]=s[0]+bb0.x; b[1]=s[1]+bb0.y; b[2]=s[2]+bb0.z; b[3]=s[3]+bb0.w;
            b[4]=s[4]+bb1.x; b[5]=s[5]+bb1.y; b[6]=s[6]+bb1.z; b[7]=s[7]+bb1.w;
        }

        float m1 = NEG_INF_F, m2 = NEG_INF_F;
#pragma unroll
        for (int j = 0; j < 8; ++j) {
            float v = b[j];
            if (v > m1) { m2 = m1; m1 = v; }
            else if (v > m2) { m2 = v; }
        }
#pragma unroll
        for (int off = 1; off <= 2; off <<= 1) {
            float o1 = __shfl_xor_sync(0xffffffffu, m1, off);
            float o2 = __shfl_xor_sync(0xffffffffu, m2, off);
            if (o1 > m1) { m2 = fmaxf(m1, o2); m1 = o1; }
            else         { m2 = fmaxf(m2, o1); }
        }
        const float gsc = m1 + m2;
        const int myg = lane >> 2;

        int rank = 0;
#pragma unroll
        for (int g2 = 0; g2 < N_GROUPS; ++g2) {
            float og = __shfl_sync(0xffffffffu, gsc, g2 * 4);
            rank += (og > gsc) || (og == gsc && g2 < myg);
        }
        const bool kept = rank < TOPK_GROUPS;

        uint32_t key[8];
#pragma unroll
        for (int j = 0; j < 8; ++j) key[j] = fkey(b[j]);
        uint32_t mask = kept ? 0xFFu : 0u;

        float topw[TOPK]; int topi[TOPK];
        float wsum = 0.f;
#pragma unroll
        for (int it = 0; it < TOPK; ++it) {
            uint32_t bk = 0; uint32_t be = 0x7fffffffu; float bs = 0.f;
#pragma unroll
            for (int j = 0; j < 8; ++j) {
                const bool live = (mask >> j) & 1u;
                if (live && key[j] > bk) { bk = key[j]; be = lane * 8 + j; bs = s[j]; }
            }
#pragma unroll
            for (int off = 16; off; off >>= 1) {
                uint32_t ok = __shfl_xor_sync(0xffffffffu, bk, off);
                uint32_t oe = __shfl_xor_sync(0xffffffffu, be, off);
                float    os = __shfl_xor_sync(0xffffffffu, bs, off);
                if (ok > bk || (ok == bk && oe < be)) { bk = ok; be = oe; bs = os; }
            }
            topw[it] = bs; topi[it] = (int)be; wsum += bs;
            if ((be >> 3) == (uint32_t)lane) mask &= ~(1u << (be & 7u));
        }

        const float scale = ROUTE_SCALE / fmaxf(wsum, 1e-10f);
        if (lane == 0) {
            const size_t t = (size_t)mt_blk * 32 + row;
#pragma unroll
            for (int j = 0; j < TOPK; ++j) {
                out_w[t * TOPK + j] = topw[j] * scale;
                out_i[t * TOPK + j] = (float)topi[j];
            }
        }
    }
}

// ---------------------------------------------------------------------------
extern "C" void kernel_launch(void* const* d_in, const int* in_sizes, int n_in,
                              void* d_out, int out_size)
{
    const float* x    = (const float*)d_in[0];
    const float* w    = (const float*)d_in[1];
    const float* bias = (const float*)d_in[2];

    int T = in_sizes[0] / DIM_K;
    if (T > MAX_T) T = MAX_T;

    float* out_w = (float*)d_out;
    float* out_i = (float*)d_out + (size_t)T * TOPK;

    wsplit_kernel<<<1024, 256>>>(w);

    cudaFuncSetAttribute(fused_kernel,
                         cudaFuncAttributeMaxDynamicSharedMemorySize, SMEM_BYTES);
    fused_kernel<<<T / 32, NTHREADS, SMEM_BYTES>>>(x, bias, out_w, out_i);
}

// round 14
// speedup vs baseline: 1.5667x; 1.5667x over previous
#include <cuda_runtime.h>
#include <cuda_fp16.h>
#include <math.h>
#include <stdint.h>

// ---------------------------------------------------------------------------
// AuxLossFreeGate, fused GEMM+gate:
//   CTA = 32 tokens x 256 experts, 256 threads, 2 CTAs/SM.
//   A: fp16-split in-kernel, staged in SMEM in GROUPS of 4 chunks between
//      __syncthreads (16 barriers total, double-grouped regions).
//   B: per-warp private cp.async double-buffer from pre-split W image
//      (warp-local wait_group+syncwarp only; validated round 13).
//   3 fp16 planes (v = v1 + v2*2^-12), per-accumulator order unchanged
//   since round 6 -> bit-identical output (rel_err canary 1.782608e-07).
// ---------------------------------------------------------------------------

#define N_EXPERTS   256
#define DIM_K       2048
#define N_GROUPS    8
#define TOPK        8
#define TOPK_GROUPS 4
#define ROUTE_SCALE 2.5f
#define MAX_T       32768
#define NEG_INF_F   (-1e30f)

// ---------------- GEMM config ----------------
#define KC       32
#define NCHUNK   (DIM_K / KC)             // 64
#define AGROUP   4                        // chunks per barrier group
#define NGRP     (NCHUNK / AGROUP)        // 16
#define ABLK     144
#define APL      576                      // u32 per A plane per chunk (4*ABLK)
#define ASLOT    1152                     // u32 per A chunk (2 planes)
#define AREG     (2 * AGROUP * ASLOT)     // 9216 u32 (two 4-chunk groups)
// B image: BBLK=64, [chunk(64)][plane(2)][nt*2+ks(64)][64]
#define BBLK     64
#define BPLANE   4096
#define BCHUNK   8192
#define WSLICE   512                      // u32 per warp per plane per chunk
#define WBUF     1024                     // u32 per warp per buffer
#define BOFF     AREG                     // B region starts after A
#define SMEM_U32 (AREG + 2 * 8 * WBUF)    // 9216 + 16384 = 25600 u32
#define SMEM_BYTES (SMEM_U32 * 4)         // 102400 B
#define SC_STRIDE 264

#define NTHREADS 256

__device__ __align__(16) uint32_t g_wimg[NCHUNK * BCHUNK];

#define MMA_F16(d, a, b) asm volatile( \
    "mma.sync.aligned.m16n8k16.row.col.f32.f16.f16.f32 " \
    "{%0,%1,%2,%3},{%4,%5,%6,%7},{%8,%9},{%0,%1,%2,%3};" \
    : "+f"((d)[0]), "+f"((d)[1]), "+f"((d)[2]), "+f"((d)[3]) \
    : "r"((a).x), "r"((a).y), "r"((a).z), "r"((a).w), "r"((b).x), "r"((b).y))

#define CP_ASYNC16(dst_u32, src_ptr) \
    asm volatile("cp.async.cg.shared.global [%0], [%1], 16;" \
                 :: "r"(dst_u32), "l"(src_ptr) : "memory")
#define CP_COMMIT()  asm volatile("cp.async.commit_group;" ::: "memory")
#define CP_WAIT0()   asm volatile("cp.async.wait_group 0;" ::: "memory")
#define CP_WAIT1()   asm volatile("cp.async.wait_group 1;" ::: "memory")

__device__ __forceinline__ uint32_t smem_to_u32(const void* p) {
    uint32_t a;
    asm("{ .reg .u64 t; cvta.to.shared.u64 t, %1; cvt.u32.u64 %0, t; }" : "=r"(a) : "l"(p));
    return a;
}

// fp16 2-way split of a float pair (identical numerics since round 6).
__device__ __forceinline__ void hsplit2(float x, float y, uint32_t& p1, uint32_t& p2)
{
    __half2 h1 = __floats2half2_rn(x, y);
    p1 = *(uint32_t*)&h1;
    float rx = (x - __half2float(__low2half(h1)))  * 4096.0f;
    float ry = (y - __half2float(__high2half(h1))) * 4096.0f;
    __half2 h2 = __floats2half2_rn(rx, ry);
    p2 = *(uint32_t*)&h2;
}

__device__ __forceinline__ float sigf(float v) { return 1.0f / (1.0f + expf(-v)); }

__device__ __forceinline__ uint32_t fkey(float f) {
    uint32_t u = __float_as_uint(f);
    return u ^ (uint32_t)(((int32_t)u >> 31) | 0x80000000);
}

// ---------------------------------------------------------------------------
// Kernel 0: pre-split W (BBLK=64 image; validated round 13).
// ---------------------------------------------------------------------------
__global__ __launch_bounds__(256)
void wsplit_kernel(const float* __restrict__ W)
{
    const int gid = blockIdx.x * 256 + threadIdx.x;
    const int n = gid >> 10;
    const int p = gid & 1023;
    const int k = 2 * p;

    float2 w = *(const float2*)(W + (size_t)n * DIM_K + k);
    uint32_t p1, p2;
    hsplit2(w.x, w.y, p1, p2);

    const int nt = n >> 3;
    const int cn = n & 7;
    const int c  = k >> 5;
    const int kk = k & 31;
    const int ks = kk >> 4;
    const int kb = kk & 15;
    const int slot = cn * 4 + ((kb >> 1) & 3);
    const int reg  = kb >> 3;

    const int base = c * BCHUNK + (nt * 2 + ks) * BBLK + slot * 2 + reg;
    g_wimg[base]          = p1;
    g_wimg[base + BPLANE] = p2;
}

// ---------------------------------------------------------------------------
// Kernel 1: fused GEMM + gate.
// ---------------------------------------------------------------------------
__global__ __launch_bounds__(NTHREADS, 2)
void fused_kernel(const float* __restrict__ X, const float* __restrict__ bias,
                  float* __restrict__ out_w, float* __restrict__ out_i)
{
    extern __shared__ uint32_t sm[];
    const uint32_t smem_base = smem_to_u32(sm);
    const int tid  = threadIdx.x;
    const int warp = tid >> 5;
    const int lane = tid & 31;

    const int mt_blk = blockIdx.x;                  // 32-token tile
    const float* xb = X + (size_t)mt_blk * 32 * DIM_K;

    // A loader geometry (one float4 per thread per chunk; round-12 formula)
    int goff, aad;
    {
        const int row = tid >> 3;                   // 0..31
        const int c4  = (tid & 7) * 4;
        goff = row * DIM_K + c4;
        const int ks = c4 >> 4;
        const int kb = c4 & 15;
        const int tc = (kb >> 1) & 3;
        const int mt = row >> 4, r = row & 15;
        const int slot = (r & 7) * 4 + tc;
        const int reg  = (r >> 3) + 2 * ((kb >> 3) & 1);
        aad = (mt * 2 + ks) * ABLK + slot * 4 + (slot >> 3) * 4 + reg;
    }

    float accM[2][4][4], accS[2][4][4];
#pragma unroll
    for (int mi = 0; mi < 2; ++mi)
#pragma unroll
        for (int ni = 0; ni < 4; ++ni)
#pragma unroll
            for (int q = 0; q < 4; ++q) { accM[mi][ni][q] = 0.f; accS[mi][ni][q] = 0.f; }

    // per-warp B buffers
    const uint32_t wreg[2] = { smem_base + (BOFF + warp * WBUF) * 4,
                               smem_base + (BOFF + (8 + warp) * WBUF) * 4 };
    const uint32_t* wsrc = g_wimg + warp * WSLICE;

    // ---- prologue: issue B(0); load A group 0 ----
#pragma unroll
    for (int q = 0; q < 2; ++q)
#pragma unroll
        for (int j = 0; j < 4; ++j)
            CP_ASYNC16(wreg[0] + (q * WSLICE + j * 128 + lane * 4) * 4,
                       wsrc + q * BPLANE + j * 128 + lane * 4);
    CP_COMMIT();

    float4 ra[AGROUP];
#pragma unroll
    for (int j = 0; j < AGROUP; ++j)
        ra[j] = *(const float4*)(xb + goff + j * KC);

    for (int g = 0; g < NGRP; ++g) {
        // ---- split + store A group g into region g&1 ----
        const int abase = (g & 1) * (AGROUP * ASLOT);
#pragma unroll
        for (int j = 0; j < AGROUP; ++j) {
            uint32_t* slot = sm + abase + j * ASLOT;
            uint32_t p1a, p2a, p1b, p2b;
            hsplit2(ra[j].x, ra[j].y, p1a, p2a);
            hsplit2(ra[j].z, ra[j].w, p1b, p2b);
            slot[aad]           = p1a;
            slot[aad + 4]       = p1b;
            slot[aad + APL]     = p2a;
            slot[aad + APL + 4] = p2b;
        }
        __syncthreads();

        // ---- prefetch A group g+1 (latency hidden by 4 chunks of compute) --
        if (g + 1 < NGRP) {
            const int k0 = (g + 1) * AGROUP * KC;
#pragma unroll
            for (int j = 0; j < AGROUP; ++j)
                ra[j] = *(const float4*)(xb + goff + k0 + j * KC);
        }

        // ---- compute 4 chunks, warp-autonomous B flow ----
#pragma unroll
        for (int cc = 0; cc < AGROUP; ++cc) {
            const int c = g * AGROUP + cc;
            const uint32_t wr = wreg[c & 1];

            if (c + 1 < NCHUNK) {
                const uint32_t wn = wreg[(c + 1) & 1];
                const uint32_t* src = wsrc + (c + 1) * BCHUNK;
#pragma unroll
                for (int q = 0; q < 2; ++q)
#pragma unroll
                    for (int j = 0; j < 4; ++j)
                        CP_ASYNC16(wn + (q * WSLICE + j * 128 + lane * 4) * 4,
                                   src + q * BPLANE + j * 128 + lane * 4);
                CP_COMMIT();
                CP_WAIT1();                          // B(c) complete
            } else {
                CP_WAIT0();
            }
            __syncwarp();

            const uint32_t* aslot = sm + abase + cc * ASLOT;
#pragma unroll
            for (int ks = 0; ks < 2; ++ks) {
                uint4 af[2][2];                      // [plane][m-tile]
#pragma unroll
                for (int p = 0; p < 2; ++p)
#pragma unroll
                    for (int mi = 0; mi < 2; ++mi)
                        af[p][mi] = *(const uint4*)&aslot[p * APL +
                            (mi * 2 + ks) * ABLK + lane * 4 + (lane >> 3) * 4];

                uint2 bf[4][2];                      // [n-tile][plane]
#pragma unroll
                for (int ni = 0; ni < 4; ++ni) {
                    const uint32_t off = ((ni * 2 + ks) * BBLK + lane * 2) * 4;
                    asm volatile("ld.shared.v2.u32 {%0, %1}, [%2];"
                                 : "=r"(bf[ni][0].x), "=r"(bf[ni][0].y)
                                 : "r"(wr + off));
                    asm volatile("ld.shared.v2.u32 {%0, %1}, [%2];"
                                 : "=r"(bf[ni][1].x), "=r"(bf[ni][1].y)
                                 : "r"(wr + WSLICE * 4 + off));
                }
#pragma unroll
                for (int mi = 0; mi < 2; ++mi)
#pragma unroll
                    for (int ni = 0; ni < 4; ++ni)
                        MMA_F16(accM[mi][ni], af[0][mi], bf[ni][0]);
#pragma unroll
                for (int mi = 0; mi < 2; ++mi)
#pragma unroll
                    for (int ni = 0; ni < 4; ++ni)
                        MMA_F16(accS[mi][ni], af[0][mi], bf[ni][1]);
#pragma unroll
                for (int mi = 0; mi < 2; ++mi)
#pragma unroll
                    for (int ni = 0; ni < 4; ++ni)
                        MMA_F16(accS[mi][ni], af[1][mi], bf[ni][0]);
            }
        }
    }

    // ---- epilogue 1: sigmoid scores -> SMEM overlay (32 x 256) ----
    __syncthreads();                                 // A/B regions dead
    float* scs = (float*)sm;
    const float INV = 1.0f / 4096.0f;
    const int rbase = lane >> 2;
    const int cbase = warp * 32 + (lane & 3) * 2;
#pragma unroll
    for (int mi = 0; mi < 2; ++mi) {
#pragma unroll
        for (int ni = 0; ni < 4; ++ni) {
            const int rr = rbase + mi * 16;
            const int cc = cbase + ni * 8;
            float2 v0, v1;
            v0.x = sigf(fmaf(accS[mi][ni][0], INV, accM[mi][ni][0]));
            v0.y = sigf(fmaf(accS[mi][ni][1], INV, accM[mi][ni][1]));
            v1.x = sigf(fmaf(accS[mi][ni][2], INV, accM[mi][ni][2]));
            v1.y = sigf(fmaf(accS[mi][ni][3], INV, accM[mi][ni][3]));
            *(float2*)&scs[rr * SC_STRIDE + cc] = v0;
            *(float2*)&scs[(rr + 8) * SC_STRIDE + cc] = v1;
        }
    }
    __syncthreads();

    // ---- epilogue 2: gate 4 tokens per warp (validated logic) ----
    float4 bb0 = *(const float4*)(bias + lane * 8);
    float4 bb1 = *(const float4*)(bias + lane * 8 + 4);

    for (int tt = 0; tt < 4; ++tt) {
        const int row = warp * 4 + tt;
        const float* srow = scs + row * SC_STRIDE;

        float s[8], b[8];
        {
            float4 s0 = *(const float4*)(srow + lane * 8);
            float4 s1 = *(const float4*)(srow + lane * 8 + 4);
            s[0]=s0.x; s[1]=s0.y; s[2]=s0.z; s[3]=s0.w;
            s[4]=s1.x; s[5]=s1.y; s[6]=s1.z; s[7]=s1.w;
            b[0]=s[0]+bb0.x; b[1]=s[1]+bb0.y; b[2]=s[2]+bb0.z; b[3]=s[3]+bb0.w;
            b[4]=s[4]+bb1.x; b[5]=s[5]+bb1.y; b[6]=s[6]+bb1.z; b[7]=s[7]+bb1.w;
        }

        float m1 = NEG_INF_F, m2 = NEG_INF_F;
#pragma unroll
        for (int j = 0; j < 8; ++j) {
            float v = b[j];
            if (v > m1) { m2 = m1; m1 = v; }
            else if (v > m2) { m2 = v; }
        }
#pragma unroll
        for (int off = 1; off <= 2; off <<= 1) {
            float o1 = __shfl_xor_sync(0xffffffffu, m1, off);
            float o2 = __shfl_xor_sync(0xffffffffu, m2, off);
            if (o1 > m1) { m2 = fmaxf(m1, o2); m1 = o1; }
            else         { m2 = fmaxf(m2, o1); }
        }
        const float gsc = m1 + m2;
        const int myg = lane >> 2;

        int rank = 0;
#pragma unroll
        for (int g2 = 0; g2 < N_GROUPS; ++g2) {
            float og = __shfl_sync(0xffffffffu, gsc, g2 * 4);
            rank += (og > gsc) || (og == gsc && g2 < myg);
        }
        const bool kept = rank < TOPK_GROUPS;

        uint32_t key[8];
#pragma unroll
        for (int j = 0; j < 8; ++j) key[j] = fkey(b[j]);
        uint32_t mask = kept ? 0xFFu : 0u;

        float topw[TOPK]; int topi[TOPK];
        float wsum = 0.f;
#pragma unroll
        for (int it = 0; it < TOPK; ++it) {
            uint32_t bk = 0; uint32_t be = 0x7fffffffu; float bs = 0.f;
#pragma unroll
            for (int j = 0; j < 8; ++j) {
                const bool live = (mask >> j) & 1u;
                if (live && key[j] > bk) { bk = key[j]; be = lane * 8 + j; bs = s[j]; }
            }
#pragma unroll
            for (int off = 16; off; off >>= 1) {
                uint32_t ok = __shfl_xor_sync(0xffffffffu, bk, off);
                uint32_t oe = __shfl_xor_sync(0xffffffffu, be, off);
                float    os = __shfl_xor_sync(0xffffffffu, bs, off);
                if (ok > bk || (ok == bk && oe < be)) { bk = ok; be = oe; bs = os; }
            }
            topw[it] = bs; topi[it] = (int)be; wsum += bs;
            if ((be >> 3) == (uint32_t)lane) mask &= ~(1u << (be & 7u));
        }

        const float scale = ROUTE_SCALE / fmaxf(wsum, 1e-10f);
        if (lane == 0) {
            const size_t t = (size_t)mt_blk * 32 + row;
#pragma unroll
            for (int j = 0; j < TOPK; ++j) {
                out_w[t * TOPK + j] = topw[j] * scale;
                out_i[t * TOPK + j] = (float)topi[j];
            }
        }
    }
}

// ---------------------------------------------------------------------------
extern "C" void kernel_launch(void* const* d_in, const int* in_sizes, int n_in,
                              void* d_out, int out_size)
{
    const float* x    = (const float*)d_in[0];
    const float* w    = (const float*)d_in[1];
    const float* bias = (const float*)d_in[2];

    int T = in_sizes[0] / DIM_K;
    if (T > MAX_T) T = MAX_T;

    float* out_w = (float*)d_out;
    float* out_i = (float*)d_out + (size_t)T * TOPK;

    wsplit_kernel<<<1024, 256>>>(w);

    cudaFuncSetAttribute(fused_kernel,
                         cudaFuncAttributeMaxDynamicSharedMemorySize, SMEM_BYTES);
    fused_kernel<<<T / 32, NTHREADS, SMEM_BYTES>>>(x, bias, out_w, out_i);
}